// round 4
// baseline (speedup 1.0000x reference)
#include <cuda_runtime.h>
#include <float.h>

#define BATCH 8
#define CCH   192
#define OUTC  384
#define NPTS  3136
#define KNN   16
#define ROWS  (BATCH*NPTS)   /* 25088 */
#define TWO_C 384
#define NPART 392            /* 25088/64 row-partials for BN */

// ---------------- scratch (static device globals; no allocation) -------------
__device__ __align__(16) float g_xt[(size_t)BATCH*NPTS*CCH];     // (B,N,C)  19.3MB
__device__ float g_x2[ROWS];
__device__ __align__(16) float g_feat[(size_t)ROWS*TWO_C];       // (B*N,2C) 38.6MB
__device__ __align__(16) float g_y[(size_t)ROWS*OUTC];           // (B*N,OUT)38.6MB
__device__ float g_psum[NPART*OUTC];
__device__ float g_psq [NPART*OUTC];
__device__ float g_scale[OUTC];
__device__ float g_shift[OUTC];

// ---------------- K1: (B,C,N) -> (B,N,C) tiled transpose ---------------------
__global__ void k_transpose(const float* __restrict__ x) {
    __shared__ float sT[32][33];
    int b = blockIdx.z;
    int n0 = blockIdx.x * 32;
    int c0 = blockIdx.y * 32;
    int tx = threadIdx.x, ty = threadIdx.y;
    const float* xb = x + (size_t)b * CCH * NPTS;
#pragma unroll
    for (int q = 0; q < 4; q++) {
        int c = c0 + ty + 8*q;
        sT[ty + 8*q][tx] = xb[(size_t)c * NPTS + n0 + tx];
    }
    __syncthreads();
    float* xtb = g_xt + (size_t)b * NPTS * CCH;
#pragma unroll
    for (int q = 0; q < 4; q++) {
        int n = n0 + ty + 8*q;
        xtb[(size_t)n * CCH + c0 + tx] = sT[tx][ty + 8*q];
    }
}

// ---------------- K1b: squared norms per point -------------------------------
__global__ void k_x2() {
    int row  = blockIdx.x * 8 + (threadIdx.x >> 5);
    int lane = threadIdx.x & 31;
    const float* r = g_xt + (size_t)row * CCH;
    float s = 0.f;
#pragma unroll
    for (int c = lane; c < CCH; c += 32) { float v = r[c]; s = fmaf(v, v, s); }
#pragma unroll
    for (int o = 16; o; o >>= 1) s += __shfl_down_sync(0xffffffffu, s, o);
    if (lane == 0) g_x2[row] = s;
}

// ---------------- K2: fused distance-GEMM + top-K + maxrel + feat ------------
// Block: 256 threads handles 32 query rows of one batch, streams all 3136
// candidates in 64-wide tiles. score_j = x2[j] - 2*<x_i,x_j>  (same ranking
// as the reference distance). Top-16-smallest kept per row in registers.
__global__ void __launch_bounds__(256) k_knn_feat() {
    __shared__ float sXi[32*193];   // the block's 32 query rows, full C (persistent)
    __shared__ float sXj[32*66];    // [k][j] candidate chunk
    __shared__ float sS[32*68];     // scores tile [i][j]
    __shared__ float sx2[64];
    __shared__ int   sTop[32*KNN];

    int b = blockIdx.y;
    int ibase = blockIdx.x * 32;
    const float* xtb = g_xt + (size_t)b * NPTS * CCH;
    const float* x2b = g_x2 + b * NPTS;

    int t  = threadIdx.x;
    int tx = t & 15, ty = t >> 4;
    int i0 = 2*ty, i1 = i0 + 1;
    int jc = tx * 4;

    // load the 32 query rows once (coalesced)
#pragma unroll
    for (int q = 0; q < 24; q++) {
        int idx = t + q*256;
        int c = idx % CCH, i = idx / CCH;
        sXi[i*193 + c] = xtb[(size_t)(ibase + i)*CCH + c];
    }

    float tval[KNN]; int tidx[KNN];
    float tmax = FLT_MAX; int targ = 0;
#pragma unroll
    for (int k = 0; k < KNN; k++) { tval[k] = FLT_MAX; tidx[k] = 0; }

    __syncthreads();

    for (int jb = 0; jb < NPTS; jb += 64) {
        if (t < 64) sx2[t] = x2b[jb + t];
        float acc[2][4] = {{0.f,0.f,0.f,0.f},{0.f,0.f,0.f,0.f}};
        for (int kc = 0; kc < CCH; kc += 32) {
            __syncthreads();
#pragma unroll
            for (int q = 0; q < 8; q++) {
                int idx = t + q*256;
                int k = idx & 31, j = idx >> 5;
                sXj[k*66 + j] = xtb[(size_t)(jb + j)*CCH + kc + k];
            }
            __syncthreads();
#pragma unroll
            for (int k = 0; k < 32; k++) {
                float a0 = sXi[i0*193 + kc + k];
                float a1 = sXi[i1*193 + kc + k];
                float2 b01 = *(const float2*)&sXj[k*66 + jc];
                float2 b23 = *(const float2*)&sXj[k*66 + jc + 2];
                acc[0][0] = fmaf(a0, b01.x, acc[0][0]);
                acc[0][1] = fmaf(a0, b01.y, acc[0][1]);
                acc[0][2] = fmaf(a0, b23.x, acc[0][2]);
                acc[0][3] = fmaf(a0, b23.y, acc[0][3]);
                acc[1][0] = fmaf(a1, b01.x, acc[1][0]);
                acc[1][1] = fmaf(a1, b01.y, acc[1][1]);
                acc[1][2] = fmaf(a1, b23.x, acc[1][2]);
                acc[1][3] = fmaf(a1, b23.y, acc[1][3]);
            }
        }
        // finalize scores into smem
        {
            float4 s0, s1;
            s0.x = sx2[jc+0] - 2.f*acc[0][0];
            s0.y = sx2[jc+1] - 2.f*acc[0][1];
            s0.z = sx2[jc+2] - 2.f*acc[0][2];
            s0.w = sx2[jc+3] - 2.f*acc[0][3];
            s1.x = sx2[jc+0] - 2.f*acc[1][0];
            s1.y = sx2[jc+1] - 2.f*acc[1][1];
            s1.z = sx2[jc+2] - 2.f*acc[1][2];
            s1.w = sx2[jc+3] - 2.f*acc[1][3];
            *(float4*)&sS[i0*68 + jc] = s0;
            *(float4*)&sS[i1*68 + jc] = s1;
        }
        __syncthreads();
        // per-row serial top-K update (threads 0..31, one row each; inserts rare)
        if (t < 32) {
            const float* row = &sS[t*68];
            for (int j = 0; j < 64; j++) {
                float s = row[j];
                if (s < tmax) {
#pragma unroll
                    for (int k = 0; k < KNN; k++)
                        if (k == targ) { tval[k] = s; tidx[k] = jb + j; }
                    tmax = -FLT_MAX;
#pragma unroll
                    for (int k = 0; k < KNN; k++)
                        if (tval[k] > tmax) { tmax = tval[k]; targ = k; }
                }
            }
        }
        __syncthreads();
    }

    if (t < 32) {
#pragma unroll
        for (int k = 0; k < KNN; k++) sTop[t*KNN + k] = tidx[k];
    }
    __syncthreads();

    // gather neighbors, max-relative, write interleaved (x, maxrel) feature
    float2* featb = (float2*)g_feat + (size_t)(b*NPTS + ibase) * CCH;
    for (int r = 0; r < 32; r++) {
        if (t < CCH) {
            float xi = sXi[r*193 + t];
            float m = -FLT_MAX;
#pragma unroll
            for (int k = 0; k < KNN; k++) {
                int j = sTop[r*KNN + k];
                m = fmaxf(m, xtb[(size_t)j*CCH + t]);
            }
            featb[(size_t)r*CCH + t] = make_float2(xi, m - xi);
        }
    }
}

// ---------------- K3: y = feat @ w^T + b  (25088 x 384 x 384) ----------------
__global__ void __launch_bounds__(256) k_gemm(const float* __restrict__ w,
                                              const float* __restrict__ bias) {
    __shared__ float sA[64*33];  // [m][k]
    __shared__ float sB[32*66];  // [k][o]
    int r0 = blockIdx.x * 64;
    int o0 = blockIdx.y * 64;
    int t  = threadIdx.x;
    int tx = t & 15, ty = t >> 4;
    int oc = tx*4, mc = ty*4;
    float acc[4][4] = {};
    for (int kc = 0; kc < TWO_C; kc += 32) {
        __syncthreads();
#pragma unroll
        for (int q = 0; q < 8; q++) {
            int idx = t + q*256;
            int k = idx & 31, m = idx >> 5;
            sA[m*33 + k] = g_feat[(size_t)(r0 + m)*TWO_C + kc + k];
        }
#pragma unroll
        for (int q = 0; q < 8; q++) {
            int idx = t + q*256;
            int k = idx & 31, o = idx >> 5;
            sB[k*66 + o] = w[(size_t)(o0 + o)*TWO_C + kc + k];
        }
        __syncthreads();
#pragma unroll
        for (int k = 0; k < 32; k++) {
            float2 b01 = *(const float2*)&sB[k*66 + oc];
            float2 b23 = *(const float2*)&sB[k*66 + oc + 2];
#pragma unroll
            for (int q = 0; q < 4; q++) {
                float a = sA[(mc+q)*33 + k];
                acc[q][0] = fmaf(a, b01.x, acc[q][0]);
                acc[q][1] = fmaf(a, b01.y, acc[q][1]);
                acc[q][2] = fmaf(a, b23.x, acc[q][2]);
                acc[q][3] = fmaf(a, b23.y, acc[q][3]);
            }
        }
    }
#pragma unroll
    for (int q = 0; q < 4; q++) {
        float4 v;
        v.x = acc[q][0] + bias[o0+oc+0];
        v.y = acc[q][1] + bias[o0+oc+1];
        v.z = acc[q][2] + bias[o0+oc+2];
        v.w = acc[q][3] + bias[o0+oc+3];
        *(float4*)&g_y[(size_t)(r0+mc+q)*OUTC + o0 + oc] = v;
    }
}

// ---------------- K4: deterministic per-channel partial sums -----------------
__global__ void k_partial() {
    int r0 = blockIdx.x * 64;
    int t  = threadIdx.x;  // 128 threads, 3 channels each
    float s[3] = {0,0,0}, q2[3] = {0,0,0};
    for (int rr = 0; rr < 64; rr++) {
        const float* row = g_y + (size_t)(r0+rr)*OUTC;
#pragma unroll
        for (int c = 0; c < 3; c++) {
            float v = row[t + 128*c];
            s[c]  += v;
            q2[c] = fmaf(v, v, q2[c]);
        }
    }
#pragma unroll
    for (int c = 0; c < 3; c++) {
        g_psum[blockIdx.x*OUTC + t + 128*c] = s[c];
        g_psq [blockIdx.x*OUTC + t + 128*c] = q2[c];
    }
}

// ---------------- K4b: finalize BN scale/shift -------------------------------
__global__ void k_stats(const float* __restrict__ gamma,
                        const float* __restrict__ beta) {
    int o = threadIdx.x;
    float S = 0.f, Q = 0.f;
    for (int p = 0; p < NPART; p++) { S += g_psum[p*OUTC + o]; Q += g_psq[p*OUTC + o]; }
    float inv  = 1.f / (float)ROWS;
    float mean = S * inv;
    float var  = Q * inv - mean*mean;
    float sc   = gamma[o] * rsqrtf(var + 1e-5f);
    g_scale[o] = sc;
    g_shift[o] = beta[o] - mean * sc;
}

// ---------------- K5: normalize + ReLU + transpose to (B,OUT,N) --------------
__global__ void k_out(float* __restrict__ out) {
    __shared__ float sT[32][33];
    int b  = blockIdx.z;
    int n0 = blockIdx.x * 32;
    int o0 = blockIdx.y * 32;
    int tx = threadIdx.x, ty = threadIdx.y;
    {
        int o = o0 + tx;
        float sc = g_scale[o], sh = g_shift[o];
#pragma unroll
        for (int q = 0; q < 4; q++) {
            int n = n0 + ty + 8*q;
            float v = g_y[(size_t)(b*NPTS + n)*OUTC + o];
            sT[ty+8*q][tx] = fmaxf(fmaf(v, sc, sh), 0.f);
        }
    }
    __syncthreads();
#pragma unroll
    for (int q = 0; q < 4; q++) {
        int o = o0 + ty + 8*q;
        out[((size_t)b*OUTC + o)*NPTS + n0 + tx] = sT[tx][ty+8*q];
    }
}

// ---------------- launch -----------------------------------------------------
extern "C" void kernel_launch(void* const* d_in, const int* in_sizes, int n_in,
                              void* d_out, int out_size) {
    const float* x     = (const float*)d_in[0];
    const float* w     = (const float*)d_in[1];
    const float* bias  = (const float*)d_in[2];
    const float* gamma = (const float*)d_in[3];
    const float* beta  = (const float*)d_in[4];
    float* out = (float*)d_out;

    k_transpose<<<dim3(98, 6, 8), dim3(32, 8)>>>(x);
    k_x2<<<3136, 256>>>();
    k_knn_feat<<<dim3(98, 8), 256>>>();
    k_gemm<<<dim3(392, 6), 256>>>(w, bias);
    k_partial<<<NPART, 128>>>();
    k_stats<<<1, OUTC>>>(gamma, beta);
    k_out<<<dim3(98, 12, 8), dim3(32, 8)>>>(out);
}